// round 1
// baseline (speedup 1.0000x reference)
#include <cuda_runtime.h>

// NCC loss, 9x9 box window, SAME zero padding, n = 81 fixed (matches reference conv).
// loss = mean over all pixels of (2 - cc1 - cc2)/2,
//   cc  = cross^2 / (varI * varJ + 1e-5)
//   cross = S_IJ - S_I*S_J/81, var = S_XX - S_X^2/81
//
// Fused single-pass kernel:
//   grid (4 col-blocks, 4 row-strips, 32 batches) = 512 blocks x 128 threads.
//   Each thread owns one image column; vertical sliding window with a 9-deep
//   register ring of the 8 horizontal field sums (static indices via 9-unroll).
//   Raw input rows staged in double-buffered smem (1 barrier / row-step).
// Deterministic reduction: per-block partials -> fixed-order tree reduce.

#define WW 512
#define HH 512
#define NB 32
#define COLS 128
#define ROWS_PER 128
#define NBLK (4 * 4 * 32)

__device__ float g_partials[NBLK];

__global__ __launch_bounds__(128, 4)
void ncc_main(const float* __restrict__ img1,
              const float* __restrict__ img2,
              const float* __restrict__ fus)
{
    const int tid   = threadIdx.x;
    const int xbase = blockIdx.x * COLS;
    const int ybase = blockIdx.y * ROWS_PER;
    const int b     = blockIdx.z;

    const size_t base = (size_t)b * (size_t)(HH * WW);
    const float* p1 = img1 + base;
    const float* p2 = img2 + base;
    const float* pf = fus  + base;

    __shared__ float rows[2][3][COLS + 8];   // 136 staged values per image
    __shared__ float wsum[4];

    // 9-row ring of horizontal sums for the 8 fields + vertical running sums
    float ring[9][8];
    float S[8];
#pragma unroll
    for (int j = 0; j < 9; ++j)
#pragma unroll
        for (int q = 0; q < 8; ++q) ring[j][q] = 0.0f;
#pragma unroll
    for (int q = 0; q < 8; ++q) S[q] = 0.0f;

    float acc = 0.0f;
    const float inv_n = 1.0f / 81.0f;

    // 144 steps = 16 * 9 so the ring index (sub) is a compile-time constant.
    // Real steps are 0..135 (input rows ybase-4 .. ybase+131); steps 136..143
    // are padding (loads predicated to zero, outputs guarded off).
    for (int s9 = 0; s9 < 16; ++s9) {
#pragma unroll
        for (int sub = 0; sub < 9; ++sub) {
            const int step = s9 * 9 + sub;
            const int r    = ybase - 4 + step;
            const bool rok = (r >= 0) && (r < HH);
            const int buf  = step & 1;

            // ---- stage row r (136 wide, zero-padded) ----
            {
                const long rowoff = (long)r * WW;
                int  gx = xbase - 4 + tid;
                bool ok = rok && (gx >= 0) && (gx < WW);
                long idx = rowoff + gx;
                rows[buf][0][tid] = ok ? __ldg(p1 + idx) : 0.0f;
                rows[buf][1][tid] = ok ? __ldg(p2 + idx) : 0.0f;
                rows[buf][2][tid] = ok ? __ldg(pf + idx) : 0.0f;
                if (tid < 8) {
                    int  pos = COLS + tid;             // 128..135
                    int  gx2 = xbase - 4 + pos;        // >= 124, check upper only
                    bool ok2 = rok && (gx2 < WW);
                    long idx2 = rowoff + gx2;
                    rows[buf][0][pos] = ok2 ? __ldg(p1 + idx2) : 0.0f;
                    rows[buf][1][pos] = ok2 ? __ldg(p2 + idx2) : 0.0f;
                    rows[buf][2][pos] = ok2 ? __ldg(pf + idx2) : 0.0f;
                }
            }
            __syncthreads();

            // ---- horizontal 9-tap sums of the 8 fields for my column ----
            float h0 = 0.f, h1 = 0.f, h2 = 0.f, h3 = 0.f;
            float h4 = 0.f, h5 = 0.f, h6 = 0.f, h7 = 0.f;
#pragma unroll
            for (int k = 0; k < 9; ++k) {
                float a = rows[buf][0][tid + k];
                float c = rows[buf][1][tid + k];
                float f = rows[buf][2][tid + k];
                h0 += a;
                h1 = fmaf(a, a, h1);
                h2 = fmaf(a, f, h2);
                h3 += c;
                h4 = fmaf(c, c, h4);
                h5 = fmaf(c, f, h5);
                h6 += f;
                h7 = fmaf(f, f, h7);
            }
            float h[8] = {h0, h1, h2, h3, h4, h5, h6, h7};

            // ---- vertical sliding update (static ring index = sub) ----
#pragma unroll
            for (int q = 0; q < 8; ++q) {
                S[q] += h[q] - ring[sub][q];
                ring[sub][q] = h[q];
            }

            // ---- emit output row y = ybase + step - 8 ----
            if (step >= 8 && step < ROWS_PER + 8) {
                float mA = S[0] * inv_n;   // S_I1 / n
                float mB = S[3] * inv_n;   // S_I2 / n
                float mJ = S[6] * inv_n;   // S_F  / n

                float crossA = fmaf(-mA, S[6], S[2]);
                float varA   = fmaf(-mA, S[0], S[1]);
                float varJ   = fmaf(-mJ, S[6], S[7]);
                float crossB = fmaf(-mB, S[6], S[5]);
                float varB   = fmaf(-mB, S[3], S[4]);

                float ccA = crossA * crossA * __fdividef(1.0f, fmaf(varA, varJ, 1e-5f));
                float ccB = crossB * crossB * __fdividef(1.0f, fmaf(varB, varJ, 1e-5f));
                acc += (2.0f - ccA - ccB);   // = 2 * combined
            }
            __syncthreads();   // protect smem buffer reuse (buf written again at step+2)
        }
    }

    // ---- deterministic block reduction ----
#pragma unroll
    for (int off = 16; off > 0; off >>= 1)
        acc += __shfl_xor_sync(0xffffffffu, acc, off);
    if ((tid & 31) == 0) wsum[tid >> 5] = acc;
    __syncthreads();
    if (tid == 0) {
        float t = (wsum[0] + wsum[1]) + (wsum[2] + wsum[3]);
        int bidx = (blockIdx.z * 4 + blockIdx.y) * 4 + blockIdx.x;
        g_partials[bidx] = t;
    }
}

__global__ void ncc_reduce(float* __restrict__ out)
{
    __shared__ float s[NBLK];
    const int t = threadIdx.x;
    s[t] = g_partials[t];
    __syncthreads();
#pragma unroll
    for (int off = NBLK / 2; off > 0; off >>= 1) {
        if (t < off) s[t] += s[t + off];
        __syncthreads();
    }
    if (t == 0) {
        // mean(combined) = total_sum_of(2*combined) * 0.5 / (32*512*512)
        //                = total * 2^-24   (exact constant)
        out[0] = s[0] * 5.9604644775390625e-08f;
    }
}

extern "C" void kernel_launch(void* const* d_in, const int* in_sizes, int n_in,
                              void* d_out, int out_size)
{
    (void)in_sizes; (void)n_in; (void)out_size;
    const float* img1 = (const float*)d_in[0];
    const float* img2 = (const float*)d_in[1];
    const float* fus  = (const float*)d_in[2];

    dim3 grid(4, 4, NB);   // col-blocks, row-strips, batches
    ncc_main<<<grid, 128>>>(img1, img2, fus);
    ncc_reduce<<<1, NBLK>>>((float*)d_out);
}